// round 8
// baseline (speedup 1.0000x reference)
#include <cuda_runtime.h>

#define NN 4096
#define EE 3
#define TT 5
#define DDIM 4
#define FF 64
#define HH 64
#define BB 2
#define PSTEPS 10
#define NC 8   // B*D columns of the skinny GEMM

// Persistent scratch (fully rewritten every launch -> deterministic)
__device__ __align__(16) float g_win[TT][NN][NC];       // [slot][n][b*4+d]
__device__ __align__(16) float g_PW [TT][EE][NN][NC];   // [slot][e][n][b*4+d] = A_e @ win_slot
__device__ __align__(16) float g_rowsum[EE][NN];
__device__ int g_mask[NN];

// ---- packed f32x2 helpers (sm_103a FFMA2 path) ----
__device__ __forceinline__ unsigned long long pk2(float a, float b) {
  unsigned long long r;
  asm("mov.b64 %0, {%1, %2};" : "=l"(r) : "f"(a), "f"(b));
  return r;
}
__device__ __forceinline__ void fma2(unsigned long long& d,
                                     unsigned long long a, unsigned long long b) {
  asm("fma.rn.f32x2 %0, %1, %2, %0;" : "+l"(d) : "l"(a), "l"(b));
}
__device__ __forceinline__ unsigned long long add2(unsigned long long a,
                                                   unsigned long long b) {
  unsigned long long r;
  asm("add.rn.f32x2 %0, %1, %2;" : "=l"(r) : "l"(a), "l"(b));
  return r;
}
__device__ __forceinline__ void upk2(unsigned long long v, float& lo, float& hi) {
  asm("mov.b64 {%0, %1}, %2;" : "=f"(lo), "=f"(hi) : "l"(v));
}

// ---------------------------------------------------------------------------
// Init: scatter time_segs [B,T,N,D] into window slots; zero mask.
// ---------------------------------------------------------------------------
__global__ void k_init(const float* __restrict__ ts) {
  int i = blockIdx.x * blockDim.x + threadIdx.x;
  if (i < NN) g_mask[i] = 0;
  if (i < BB * TT * NN * DDIM) {
    int d  = i & 3;
    int n  = (i >> 2) & (NN - 1);
    int bt = i >> 14;          // b*5 + t
    int t  = bt % 5;
    int b  = bt / 5;
    g_win[t][n][b * 4 + d] = ts[i];
  }
}

// ---------------------------------------------------------------------------
// Tall-skinny GEMM: g_PW[slot][e][n][c] = sum_m A[e][n][m] * g_win[slot][m][c]
// block = 128 (4 warps), warp owns 2 rows, lanes split m in float4 quads.
// X tile staged as XTp[c2][p] = (x[2c2](2p), x[2c2+1](2p), x[2c2](2p+1),
// x[2c2+1](2p+1)) -> one LDS.128 feeds 2 packed f32x2 FMAs.
// grid = EE * 512. RS pass also makes exact row sums + column-any node mask.
// ---------------------------------------------------------------------------
template <bool RS>
__global__ void __launch_bounds__(128, 5) k_gemm(const float* __restrict__ A, int slot) {
  __shared__ float4 XTp[4][512];           // 32 KB
  __shared__ unsigned s_any[4][256];       // RS only

  const float* X = &g_win[slot][0][0];
  int e    = blockIdx.x >> 9;
  int tile = blockIdx.x & 511;
  int warp = threadIdx.x >> 5, lane = threadIdx.x & 31;
  int row0 = tile * 8 + warp * 2;

  const float* Ab0 = A + (size_t)e * NN * NN + (size_t)row0 * NN;
  const float* Ab1 = Ab0 + NN;

  unsigned long long acc2[2][4];
  unsigned long long z = pk2(0.f, 0.f);
#pragma unroll
  for (int r = 0; r < 2; r++)
#pragma unroll
    for (int c = 0; c < 4; c++) acc2[r][c] = z;
  float rs0 = 0.f, rs1 = 0.f;

  for (int t0 = 0; t0 < NN; t0 += 1024) {
    __syncthreads();
    // stage X tile: X row = 8 floats = 2 float4 (h=0 -> cols 0-3, h=1 -> 4-7)
    const float4* X4 = (const float4*)(X + (size_t)t0 * NC);
    for (int i = threadIdx.x; i < 2048; i += 128) {
      float4 v = X4[i];
      int m = i >> 1, h = i & 1, p = m >> 1, half = m & 1;
      ((float2*)&XTp[2 * h + 0][p])[half] = make_float2(v.x, v.y);
      ((float2*)&XTp[2 * h + 1][p])[half] = make_float2(v.z, v.w);
    }
    __syncthreads();

    const float4* A0 = (const float4*)(Ab0 + t0);
    const float4* A1 = (const float4*)(Ab1 + t0);

#pragma unroll 2
    for (int it = 0; it < 8; it++) {
      int mq = it * 32 + lane;
      float4 a0 = __ldcs(A0 + mq);
      float4 a1 = __ldcs(A1 + mq);

      if (RS) {
        rs0 += (a0.x + a0.y) + (a0.z + a0.w);
        rs1 += (a1.x + a1.y) + (a1.z + a1.w);
        unsigned v = 0;
        if (a0.x > 0.f || a1.x > 0.f) v |= 0x1u;
        if (a0.y > 0.f || a1.y > 0.f) v |= 0x100u;
        if (a0.z > 0.f || a1.z > 0.f) v |= 0x10000u;
        if (a0.w > 0.f || a1.w > 0.f) v |= 0x1000000u;
        if (warp == 0) s_any[0][mq] = v;
        else { // OR-accumulate per warp slot; all warps cover all mq
          s_any[warp][mq] = v;
        }
      }

      unsigned long long p0x = pk2(a0.x, a0.x), p0y = pk2(a0.y, a0.y);
      unsigned long long p0z = pk2(a0.z, a0.z), p0w = pk2(a0.w, a0.w);
      unsigned long long p1x = pk2(a1.x, a1.x), p1y = pk2(a1.y, a1.y);
      unsigned long long p1z = pk2(a1.z, a1.z), p1w = pk2(a1.w, a1.w);

      int p = 2 * mq;
#pragma unroll
      for (int c2 = 0; c2 < 4; c2++) {
        ulonglong2 q0 = *(const ulonglong2*)&XTp[c2][p];
        ulonglong2 q1 = *(const ulonglong2*)&XTp[c2][p + 1];
        fma2(acc2[0][c2], p0x, q0.x);
        fma2(acc2[0][c2], p0y, q0.y);
        fma2(acc2[0][c2], p0z, q1.x);
        fma2(acc2[0][c2], p0w, q1.y);
        fma2(acc2[1][c2], p1x, q0.x);
        fma2(acc2[1][c2], p1y, q0.y);
        fma2(acc2[1][c2], p1z, q1.x);
        fma2(acc2[1][c2], p1w, q1.y);
      }
    }

    if (RS) {
      __syncthreads();
      for (int i = threadIdx.x; i < 256; i += 128) {
        unsigned v = s_any[0][i] | s_any[1][i] | s_any[2][i] | s_any[3][i];
        int mg = t0 + i * 4;
        if (v & 0x1u)        g_mask[mg + 0] = 1;   // same-value store: race-safe
        if (v & 0x100u)      g_mask[mg + 1] = 1;
        if (v & 0x10000u)    g_mask[mg + 2] = 1;
        if (v & 0x1000000u)  g_mask[mg + 3] = 1;
      }
    }
  }

  // deterministic butterfly reduction across lanes (packed adds)
#pragma unroll
  for (int r = 0; r < 2; r++)
#pragma unroll
    for (int c = 0; c < 4; c++) {
      unsigned long long v = acc2[r][c];
#pragma unroll
      for (int off = 16; off; off >>= 1)
        v = add2(v, __shfl_xor_sync(0xffffffffu, v, off));
      acc2[r][c] = v;
    }
  if (RS) {
#pragma unroll
    for (int off = 16; off; off >>= 1) {
      rs0 += __shfl_xor_sync(0xffffffffu, rs0, off);
      rs1 += __shfl_xor_sync(0xffffffffu, rs1, off);
    }
  }

  if (lane == 0) {
#pragma unroll
    for (int r = 0; r < 2; r++) {
      float o[8];
#pragma unroll
      for (int c = 0; c < 4; c++) upk2(acc2[r][c], o[2 * c], o[2 * c + 1]);
      float4* dst = (float4*)&g_PW[slot][e][row0 + r][0];
      dst[0] = make_float4(o[0], o[1], o[2], o[3]);
      dst[1] = make_float4(o[4], o[5], o[6], o[7]);
    }
    if (RS) {
      g_rowsum[e][row0 + 0] = rs0;
      g_rowsum[e][row0 + 1] = rs1;
    }
  }
}

// ---------------------------------------------------------------------------
// Fused per-node step. block = 128 (4 warps), each warp handles 4 (b,n)
// instances. Lane owns channel pair {2l, 2l+1} -> float2 weight loads.
// grid = 8192/16 = 512.
// ---------------------------------------------------------------------------
__global__ void __launch_bounds__(128) k_step(
    const float* __restrict__ conv_w, const float* __restrict__ conv_b,
    const float* __restrict__ enc_w1, const float* __restrict__ enc_w2,
    const float* __restrict__ enc_b,  const float* __restrict__ dec_w,
    const float* __restrict__ dec_b,  const float* __restrict__ out_w,
    const float* __restrict__ out_b,  float* __restrict__ dout, int s)
{
  __shared__ __align__(16) float s_win[4][4][20];
  __shared__ __align__(16) float s_pw [4][4][60];
  __shared__ __align__(16) float s_cond[4][4][64];
  __shared__ __align__(16) float s_agg [4][4][192];
  __shared__ __align__(16) float s_enc [4][4][64];

  int warp = threadIdx.x >> 5, lane = threadIdx.x & 31;
  int l2 = lane * 2;
  int base = blockIdx.x * 16 + warp * 4;

  // ---- stage window + PW values for this warp's 4 instances ----
  for (int j = lane; j < 80; j += 32) {
    int li = j / 20, k = j % 20;
    int inst = base + li;
    int b = inst >> 12, n = inst & (NN - 1);
    if (k < 5) {
      int slotv = (s + k) % 5;
      float4 v = *(const float4*)&g_win[slotv][n][b * 4];
      *(float4*)&s_win[warp][li][k * 4] = v;
    } else {
      int k2 = k - 5, e = k2 / 5, t = k2 % 5;
      int slotv = (s + t) % 5;
      float4 v = *(const float4*)&g_PW[slotv][e][n][b * 4];
      *(float4*)&s_pw[warp][li][e * 20 + t * 4] = v;
    }
  }
  __syncwarp();

  int nn[4];
#pragma unroll
  for (int i = 0; i < 4; i++) nn[i] = (base + i) & (NN - 1);

  // ---- cond + agg (20 -> 64 contractions) ----
  float2 cb = *(const float2*)&conv_b[l2];
  float cond[4][2], agg[4][3][2];
#pragma unroll
  for (int i = 0; i < 4; i++) {
    cond[i][0] = cb.x; cond[i][1] = cb.y;
#pragma unroll
    for (int e = 0; e < 3; e++) {
      float r = g_rowsum[e][nn[i]];
      agg[i][e][0] = r * cb.x; agg[i][e][1] = r * cb.y;
    }
  }
  for (int td = 0; td < 20; td++) {
    float2 cw = *(const float2*)&conv_w[td * 64 + l2];
#pragma unroll
    for (int i = 0; i < 4; i++) {
      float w = s_win[warp][i][td];
      cond[i][0] += w * cw.x; cond[i][1] += w * cw.y;
#pragma unroll
      for (int e = 0; e < 3; e++) {
        float a = s_pw[warp][i][e * 20 + td];
        agg[i][e][0] += a * cw.x; agg[i][e][1] += a * cw.y;
      }
    }
  }
#pragma unroll
  for (int i = 0; i < 4; i++) {
    *(float2*)&s_cond[warp][i][l2] = make_float2(cond[i][0], cond[i][1]);
#pragma unroll
    for (int e = 0; e < 3; e++)
      *(float2*)&s_agg[warp][i][e * 64 + l2] = make_float2(agg[i][e][0], agg[i][e][1]);
  }
  __syncwarp();

  // ---- per-edge-type GCSConv + tanh stack ----
  float encs[4][2];
#pragma unroll
  for (int i = 0; i < 4; i++) { encs[i][0] = 0.f; encs[i][1] = 0.f; }
  for (int e = 0; e < 3; e++) {
    float acc[4][2];
    float2 eb = *(const float2*)&enc_b[e * 64 + l2];
#pragma unroll
    for (int i = 0; i < 4; i++) { acc[i][0] = eb.x; acc[i][1] = eb.y; }
    for (int f = 0; f < 64; f++) {
      int wi = (e * 64 + f) * 64 + l2;
      float2 w1 = *(const float2*)&enc_w1[wi];
      float2 w2 = *(const float2*)&enc_w2[wi];
#pragma unroll
      for (int i = 0; i < 4; i++) {
        float a = s_agg[warp][i][e * 64 + f];
        float c = s_cond[warp][i][f];
        acc[i][0] += a * w1.x + c * w2.x;
        acc[i][1] += a * w1.y + c * w2.y;
      }
    }
#pragma unroll
    for (int i = 0; i < 4; i++) {
      encs[i][0] += tanhf(acc[i][0]);
      encs[i][1] += tanhf(acc[i][1]);
    }
  }
#pragma unroll
  for (int i = 0; i < 4; i++) {
    float mk = g_mask[nn[i]] ? 1.0f : 0.0f;
    *(float2*)&s_enc[warp][i][l2] =
        make_float2(tanhf(encs[i][0]) * mk, tanhf(encs[i][1]) * mk);
  }
  __syncwarp();

  // ---- decoder: relu([cond, enc] @ dec_w + dec_b) ----
  float hh[4][2];
  float2 db = *(const float2*)&dec_b[l2];
#pragma unroll
  for (int i = 0; i < 4; i++) { hh[i][0] = db.x; hh[i][1] = db.y; }
  for (int k = 0; k < 64; k++) {
    float2 dw = *(const float2*)&dec_w[k * 64 + l2];
#pragma unroll
    for (int i = 0; i < 4; i++) {
      float x = s_cond[warp][i][k];
      hh[i][0] += x * dw.x; hh[i][1] += x * dw.y;
    }
  }
  for (int k = 0; k < 64; k++) {
    float2 dw = *(const float2*)&dec_w[(64 + k) * 64 + l2];
#pragma unroll
    for (int i = 0; i < 4; i++) {
      float x = s_enc[warp][i][k];
      hh[i][0] += x * dw.x; hh[i][1] += x * dw.y;
    }
  }
#pragma unroll
  for (int i = 0; i < 4; i++) {
    hh[i][0] = fmaxf(hh[i][0], 0.f);
    hh[i][1] = fmaxf(hh[i][1], 0.f);
  }

  // ---- output projection + residual + window update ----
  float4 owa = *(const float4*)&out_w[l2 * 4];
  float4 owb = *(const float4*)&out_w[(l2 + 1) * 4];
  float ob0 = out_b[0], ob1 = out_b[1], ob2 = out_b[2], ob3 = out_b[3];
  int slot_new = s % 5;
#pragma unroll
  for (int i = 0; i < 4; i++) {
    float p0 = hh[i][0] * owa.x + hh[i][1] * owb.x;
    float p1 = hh[i][0] * owa.y + hh[i][1] * owb.y;
    float p2 = hh[i][0] * owa.z + hh[i][1] * owb.z;
    float p3 = hh[i][0] * owa.w + hh[i][1] * owb.w;
#pragma unroll
    for (int off = 16; off; off >>= 1) {
      p0 += __shfl_xor_sync(0xffffffffu, p0, off);
      p1 += __shfl_xor_sync(0xffffffffu, p1, off);
      p2 += __shfl_xor_sync(0xffffffffu, p2, off);
      p3 += __shfl_xor_sync(0xffffffffu, p3, off);
    }
    if (lane == 0) {
      int inst = base + i;
      int b = inst >> 12, n = inst & (NN - 1);
      float4 o;
      o.x = s_win[warp][i][16] + tanhf(p0 + ob0);
      o.y = s_win[warp][i][17] + tanhf(p1 + ob1);
      o.z = s_win[warp][i][18] + tanhf(p2 + ob2);
      o.w = s_win[warp][i][19] + tanhf(p3 + ob3);
      *(float4*)&g_win[slot_new][n][b * 4] = o;
      *(float4*)&dout[(size_t)((b * PSTEPS + s) * NN + n) * 4] = o;
    }
  }
}

// ---------------------------------------------------------------------------
extern "C" void kernel_launch(void* const* d_in, const int* in_sizes, int n_in,
                              void* d_out, int out_size) {
  const float* ts     = (const float*)d_in[0];
  const float* A      = (const float*)d_in[1];
  const float* conv_w = (const float*)d_in[2];
  const float* conv_b = (const float*)d_in[3];
  const float* enc_w1 = (const float*)d_in[4];
  const float* enc_w2 = (const float*)d_in[5];
  const float* enc_b  = (const float*)d_in[6];
  const float* dec_w  = (const float*)d_in[7];
  const float* dec_b  = (const float*)d_in[8];
  const float* out_w  = (const float*)d_in[9];
  const float* out_b  = (const float*)d_in[10];
  float* out = (float*)d_out;

  k_init<<<640, 256>>>(ts);
  k_gemm<true><<<EE * 512, 128>>>(A, 0);     // slot 0 + rowsum + node mask
  for (int t = 1; t < TT; t++)
    k_gemm<false><<<EE * 512, 128>>>(A, t);

  for (int s = 0; s < PSTEPS; s++) {
    k_step<<<512, 128>>>(conv_w, conv_b, enc_w1, enc_w2, enc_b,
                         dec_w, dec_b, out_w, out_b, out, s);
    if (s < PSTEPS - 1)
      k_gemm<false><<<EE * 512, 128>>>(A, s % 5);
  }
}

// round 9
// speedup vs baseline: 1.1925x; 1.1925x over previous
#include <cuda_runtime.h>

#define NN 4096
#define EE 3
#define TT 5
#define DDIM 4
#define FF 64
#define HH 64
#define BB 2
#define PSTEPS 10
#define NC 8   // B*D columns of the skinny GEMM

// Persistent scratch (fully rewritten every launch -> deterministic)
__device__ __align__(16) float g_win[TT][NN][NC];       // [slot][n][b*4+d]
__device__ __align__(16) float g_PW [TT][EE][NN][NC];   // [slot][e][n][b*4+d] = A_e @ win_slot
__device__ __align__(16) float g_rowsum[EE][NN];
__device__ int g_mask[NN];

// ---- packed f32x2 helpers (sm_103a FFMA2 path) ----
__device__ __forceinline__ unsigned long long pk2(float a, float b) {
  unsigned long long r;
  asm("mov.b64 %0, {%1, %2};" : "=l"(r) : "f"(a), "f"(b));
  return r;
}
__device__ __forceinline__ void fma2(unsigned long long& d,
                                     unsigned long long a, unsigned long long b) {
  asm("fma.rn.f32x2 %0, %1, %2, %0;" : "+l"(d) : "l"(a), "l"(b));
}
__device__ __forceinline__ unsigned long long add2(unsigned long long a,
                                                   unsigned long long b) {
  unsigned long long r;
  asm("add.rn.f32x2 %0, %1, %2;" : "=l"(r) : "l"(a), "l"(b));
  return r;
}
__device__ __forceinline__ void upk2(unsigned long long v, float& lo, float& hi) {
  asm("mov.b64 {%0, %1}, %2;" : "=f"(lo), "=f"(hi) : "l"(v));
}

// ---------------------------------------------------------------------------
// Init: scatter time_segs [B,T,N,D] into window slots; zero mask.
// ---------------------------------------------------------------------------
__global__ void k_init(const float* __restrict__ ts) {
  int i = blockIdx.x * blockDim.x + threadIdx.x;
  if (i < NN) g_mask[i] = 0;
  if (i < BB * TT * NN * DDIM) {
    int d  = i & 3;
    int n  = (i >> 2) & (NN - 1);
    int bt = i >> 14;          // b*5 + t
    int t  = bt % 5;
    int b  = bt / 5;
    g_win[t][n][b * 4 + d] = ts[i];
  }
}

// ---------------------------------------------------------------------------
// Tall-skinny GEMM over W consecutive window slots in ONE A-stream:
//   g_PW[slot+w][e][n][c] = sum_m A[e][n][m] * g_win[slot+w][m][c]
// block = 128 (4 warps), warp owns 4 rows, lanes split m in float4 quads.
// X tile = 512 m, staged packed: XTp[4w+c2][p] holds col-pair (2c2,2c2+1) of
// slot w at m=2p,2p+1 -> one LDS.128 feeds 2 packed f32x2 FMAs, reused by
// 4 rows (smem bytes = 2W x A bytes). f32x2 accumulators.
// grid = EE * 256. RS pass also emits exact row sums + column-any node mask.
// ---------------------------------------------------------------------------
template <int W, bool RS>
__global__ void __launch_bounds__(128, (W == 1 ? 5 : 4))
k_gemm(const float* __restrict__ A, int slot) {
  __shared__ float4 XTp[4 * W][256];       // 16KB * W
  __shared__ unsigned s_any[4][128];

  int e    = blockIdx.x >> 8;
  int tile = blockIdx.x & 255;
  int warp = threadIdx.x >> 5, lane = threadIdx.x & 31;
  int row0 = tile * 16 + warp * 4;

  const float* Ab0 = A + (size_t)e * NN * NN + (size_t)row0 * NN;
  const float* Ab1 = Ab0 + NN;
  const float* Ab2 = Ab1 + NN;
  const float* Ab3 = Ab2 + NN;

  unsigned long long acc2[4][4 * W];
  unsigned long long z = pk2(0.f, 0.f);
#pragma unroll
  for (int r = 0; r < 4; r++)
#pragma unroll
    for (int c = 0; c < 4 * W; c++) acc2[r][c] = z;
  float rs[4] = {0.f, 0.f, 0.f, 0.f};

  for (int t0 = 0; t0 < NN; t0 += 512) {
    __syncthreads();
    // stage X tiles for all W slots (each: 512 m x 8 cols)
    for (int i = threadIdx.x; i < 1024 * W; i += 128) {
      int w = i >> 10, j = i & 1023;
      const float4* X4 = (const float4*)(&g_win[slot + w][0][0] + (size_t)t0 * NC);
      float4 v = X4[j];
      int m = j >> 1, h = j & 1, p = m >> 1, half = m & 1;
      ((float2*)&XTp[4 * w + 2 * h + 0][p])[half] = make_float2(v.x, v.y);
      ((float2*)&XTp[4 * w + 2 * h + 1][p])[half] = make_float2(v.z, v.w);
    }
    __syncthreads();

    const float4* A0 = (const float4*)(Ab0 + t0);
    const float4* A1 = (const float4*)(Ab1 + t0);
    const float4* A2 = (const float4*)(Ab2 + t0);
    const float4* A3 = (const float4*)(Ab3 + t0);

#pragma unroll 2
    for (int it = 0; it < 4; it++) {
      int mq = it * 32 + lane;
      float4 a0 = __ldcs(A0 + mq);
      float4 a1 = __ldcs(A1 + mq);
      float4 a2 = __ldcs(A2 + mq);
      float4 a3 = __ldcs(A3 + mq);

      if (RS) {
        rs[0] += (a0.x + a0.y) + (a0.z + a0.w);
        rs[1] += (a1.x + a1.y) + (a1.z + a1.w);
        rs[2] += (a2.x + a2.y) + (a2.z + a2.w);
        rs[3] += (a3.x + a3.y) + (a3.z + a3.w);
        unsigned v = 0;
        if (a0.x > 0.f || a1.x > 0.f || a2.x > 0.f || a3.x > 0.f) v |= 0x1u;
        if (a0.y > 0.f || a1.y > 0.f || a2.y > 0.f || a3.y > 0.f) v |= 0x100u;
        if (a0.z > 0.f || a1.z > 0.f || a2.z > 0.f || a3.z > 0.f) v |= 0x10000u;
        if (a0.w > 0.f || a1.w > 0.f || a2.w > 0.f || a3.w > 0.f) v |= 0x1000000u;
        s_any[warp][mq] = v;       // every warp covers every mq of the tile
      }

      unsigned long long p0x = pk2(a0.x, a0.x), p0y = pk2(a0.y, a0.y);
      unsigned long long p0z = pk2(a0.z, a0.z), p0w = pk2(a0.w, a0.w);
      unsigned long long p1x = pk2(a1.x, a1.x), p1y = pk2(a1.y, a1.y);
      unsigned long long p1z = pk2(a1.z, a1.z), p1w = pk2(a1.w, a1.w);
      unsigned long long p2x = pk2(a2.x, a2.x), p2y = pk2(a2.y, a2.y);
      unsigned long long p2z = pk2(a2.z, a2.z), p2w = pk2(a2.w, a2.w);
      unsigned long long p3x = pk2(a3.x, a3.x), p3y = pk2(a3.y, a3.y);
      unsigned long long p3z = pk2(a3.z, a3.z), p3w = pk2(a3.w, a3.w);

      int p = 2 * mq;
#pragma unroll
      for (int wc = 0; wc < 4 * W; wc++) {
        ulonglong2 q0 = *(const ulonglong2*)&XTp[wc][p];
        ulonglong2 q1 = *(const ulonglong2*)&XTp[wc][p + 1];
        fma2(acc2[0][wc], p0x, q0.x); fma2(acc2[0][wc], p0y, q0.y);
        fma2(acc2[0][wc], p0z, q1.x); fma2(acc2[0][wc], p0w, q1.y);
        fma2(acc2[1][wc], p1x, q0.x); fma2(acc2[1][wc], p1y, q0.y);
        fma2(acc2[1][wc], p1z, q1.x); fma2(acc2[1][wc], p1w, q1.y);
        fma2(acc2[2][wc], p2x, q0.x); fma2(acc2[2][wc], p2y, q0.y);
        fma2(acc2[2][wc], p2z, q1.x); fma2(acc2[2][wc], p2w, q1.y);
        fma2(acc2[3][wc], p3x, q0.x); fma2(acc2[3][wc], p3y, q0.y);
        fma2(acc2[3][wc], p3z, q1.x); fma2(acc2[3][wc], p3w, q1.y);
      }
    }

    if (RS) {
      __syncthreads();
      for (int i = threadIdx.x; i < 128; i += 128) {
        unsigned v = s_any[0][i] | s_any[1][i] | s_any[2][i] | s_any[3][i];
        int mg = t0 + i * 4;
        if (v & 0x1u)        g_mask[mg + 0] = 1;   // same-value store: race-safe
        if (v & 0x100u)      g_mask[mg + 1] = 1;
        if (v & 0x10000u)    g_mask[mg + 2] = 1;
        if (v & 0x1000000u)  g_mask[mg + 3] = 1;
      }
    }
  }

  // deterministic butterfly reduction across lanes (packed adds)
#pragma unroll
  for (int r = 0; r < 4; r++)
#pragma unroll
    for (int c = 0; c < 4 * W; c++) {
      unsigned long long v = acc2[r][c];
#pragma unroll
      for (int off = 16; off; off >>= 1)
        v = add2(v, __shfl_xor_sync(0xffffffffu, v, off));
      acc2[r][c] = v;
    }
  if (RS) {
#pragma unroll
    for (int r = 0; r < 4; r++) {
      float v = rs[r];
#pragma unroll
      for (int off = 16; off; off >>= 1) v += __shfl_xor_sync(0xffffffffu, v, off);
      rs[r] = v;
    }
  }

  if (lane == 0) {
#pragma unroll
    for (int r = 0; r < 4; r++) {
#pragma unroll
      for (int w = 0; w < W; w++) {
        float o[8];
#pragma unroll
        for (int c = 0; c < 4; c++)
          upk2(acc2[r][4 * w + c], o[2 * c], o[2 * c + 1]);
        float4* dst = (float4*)&g_PW[slot + w][e][row0 + r][0];
        dst[0] = make_float4(o[0], o[1], o[2], o[3]);
        dst[1] = make_float4(o[4], o[5], o[6], o[7]);
      }
      if (RS) g_rowsum[e][row0 + r] = rs[r];
    }
  }
}

// ---------------------------------------------------------------------------
// Fused per-node step. block = 128 (4 warps), each warp handles 4 (b,n)
// instances. Lane owns channel pair {2l, 2l+1} -> float2 weight loads.
// grid = 8192/16 = 512.
// ---------------------------------------------------------------------------
__global__ void __launch_bounds__(128) k_step(
    const float* __restrict__ conv_w, const float* __restrict__ conv_b,
    const float* __restrict__ enc_w1, const float* __restrict__ enc_w2,
    const float* __restrict__ enc_b,  const float* __restrict__ dec_w,
    const float* __restrict__ dec_b,  const float* __restrict__ out_w,
    const float* __restrict__ out_b,  float* __restrict__ dout, int s)
{
  __shared__ __align__(16) float s_win[4][4][20];
  __shared__ __align__(16) float s_pw [4][4][60];
  __shared__ __align__(16) float s_cond[4][4][64];
  __shared__ __align__(16) float s_agg [4][4][192];
  __shared__ __align__(16) float s_enc [4][4][64];

  int warp = threadIdx.x >> 5, lane = threadIdx.x & 31;
  int l2 = lane * 2;
  int base = blockIdx.x * 16 + warp * 4;

  // ---- stage window + PW values for this warp's 4 instances ----
  for (int j = lane; j < 80; j += 32) {
    int li = j / 20, k = j % 20;
    int inst = base + li;
    int b = inst >> 12, n = inst & (NN - 1);
    if (k < 5) {
      int slotv = (s + k) % 5;
      float4 v = *(const float4*)&g_win[slotv][n][b * 4];
      *(float4*)&s_win[warp][li][k * 4] = v;
    } else {
      int k2 = k - 5, e = k2 / 5, t = k2 % 5;
      int slotv = (s + t) % 5;
      float4 v = *(const float4*)&g_PW[slotv][e][n][b * 4];
      *(float4*)&s_pw[warp][li][e * 20 + t * 4] = v;
    }
  }
  __syncwarp();

  int nn[4];
#pragma unroll
  for (int i = 0; i < 4; i++) nn[i] = (base + i) & (NN - 1);

  // ---- cond + agg (20 -> 64 contractions) ----
  float2 cb = *(const float2*)&conv_b[l2];
  float cond[4][2], agg[4][3][2];
#pragma unroll
  for (int i = 0; i < 4; i++) {
    cond[i][0] = cb.x; cond[i][1] = cb.y;
#pragma unroll
    for (int e = 0; e < 3; e++) {
      float r = g_rowsum[e][nn[i]];
      agg[i][e][0] = r * cb.x; agg[i][e][1] = r * cb.y;
    }
  }
  for (int td = 0; td < 20; td++) {
    float2 cw = *(const float2*)&conv_w[td * 64 + l2];
#pragma unroll
    for (int i = 0; i < 4; i++) {
      float w = s_win[warp][i][td];
      cond[i][0] += w * cw.x; cond[i][1] += w * cw.y;
#pragma unroll
      for (int e = 0; e < 3; e++) {
        float a = s_pw[warp][i][e * 20 + td];
        agg[i][e][0] += a * cw.x; agg[i][e][1] += a * cw.y;
      }
    }
  }
#pragma unroll
  for (int i = 0; i < 4; i++) {
    *(float2*)&s_cond[warp][i][l2] = make_float2(cond[i][0], cond[i][1]);
#pragma unroll
    for (int e = 0; e < 3; e++)
      *(float2*)&s_agg[warp][i][e * 64 + l2] = make_float2(agg[i][e][0], agg[i][e][1]);
  }
  __syncwarp();

  // ---- per-edge-type GCSConv + tanh stack ----
  float encs[4][2];
#pragma unroll
  for (int i = 0; i < 4; i++) { encs[i][0] = 0.f; encs[i][1] = 0.f; }
  for (int e = 0; e < 3; e++) {
    float acc[4][2];
    float2 eb = *(const float2*)&enc_b[e * 64 + l2];
#pragma unroll
    for (int i = 0; i < 4; i++) { acc[i][0] = eb.x; acc[i][1] = eb.y; }
    for (int f = 0; f < 64; f++) {
      int wi = (e * 64 + f) * 64 + l2;
      float2 w1 = *(const float2*)&enc_w1[wi];
      float2 w2 = *(const float2*)&enc_w2[wi];
#pragma unroll
      for (int i = 0; i < 4; i++) {
        float a = s_agg[warp][i][e * 64 + f];
        float c = s_cond[warp][i][f];
        acc[i][0] += a * w1.x + c * w2.x;
        acc[i][1] += a * w1.y + c * w2.y;
      }
    }
#pragma unroll
    for (int i = 0; i < 4; i++) {
      encs[i][0] += tanhf(acc[i][0]);
      encs[i][1] += tanhf(acc[i][1]);
    }
  }
#pragma unroll
  for (int i = 0; i < 4; i++) {
    float mk = g_mask[nn[i]] ? 1.0f : 0.0f;
    *(float2*)&s_enc[warp][i][l2] =
        make_float2(tanhf(encs[i][0]) * mk, tanhf(encs[i][1]) * mk);
  }
  __syncwarp();

  // ---- decoder: relu([cond, enc] @ dec_w + dec_b) ----
  float hh[4][2];
  float2 db = *(const float2*)&dec_b[l2];
#pragma unroll
  for (int i = 0; i < 4; i++) { hh[i][0] = db.x; hh[i][1] = db.y; }
  for (int k = 0; k < 64; k++) {
    float2 dw = *(const float2*)&dec_w[k * 64 + l2];
#pragma unroll
    for (int i = 0; i < 4; i++) {
      float x = s_cond[warp][i][k];
      hh[i][0] += x * dw.x; hh[i][1] += x * dw.y;
    }
  }
  for (int k = 0; k < 64; k++) {
    float2 dw = *(const float2*)&dec_w[(64 + k) * 64 + l2];
#pragma unroll
    for (int i = 0; i < 4; i++) {
      float x = s_enc[warp][i][k];
      hh[i][0] += x * dw.x; hh[i][1] += x * dw.y;
    }
  }
#pragma unroll
  for (int i = 0; i < 4; i++) {
    hh[i][0] = fmaxf(hh[i][0], 0.f);
    hh[i][1] = fmaxf(hh[i][1], 0.f);
  }

  // ---- output projection + residual + window update ----
  float4 owa = *(const float4*)&out_w[l2 * 4];
  float4 owb = *(const float4*)&out_w[(l2 + 1) * 4];
  float ob0 = out_b[0], ob1 = out_b[1], ob2 = out_b[2], ob3 = out_b[3];
  int slot_new = s % 5;
#pragma unroll
  for (int i = 0; i < 4; i++) {
    float p0 = hh[i][0] * owa.x + hh[i][1] * owb.x;
    float p1 = hh[i][0] * owa.y + hh[i][1] * owb.y;
    float p2 = hh[i][0] * owa.z + hh[i][1] * owb.z;
    float p3 = hh[i][0] * owa.w + hh[i][1] * owb.w;
#pragma unroll
    for (int off = 16; off; off >>= 1) {
      p0 += __shfl_xor_sync(0xffffffffu, p0, off);
      p1 += __shfl_xor_sync(0xffffffffu, p1, off);
      p2 += __shfl_xor_sync(0xffffffffu, p2, off);
      p3 += __shfl_xor_sync(0xffffffffu, p3, off);
    }
    if (lane == 0) {
      int inst = base + i;
      int b = inst >> 12, n = inst & (NN - 1);
      float4 o;
      o.x = s_win[warp][i][16] + tanhf(p0 + ob0);
      o.y = s_win[warp][i][17] + tanhf(p1 + ob1);
      o.z = s_win[warp][i][18] + tanhf(p2 + ob2);
      o.w = s_win[warp][i][19] + tanhf(p3 + ob3);
      *(float4*)&g_win[slot_new][n][b * 4] = o;
      *(float4*)&dout[(size_t)((b * PSTEPS + s) * NN + n) * 4] = o;
    }
  }
}

// ---------------------------------------------------------------------------
extern "C" void kernel_launch(void* const* d_in, const int* in_sizes, int n_in,
                              void* d_out, int out_size) {
  const float* ts     = (const float*)d_in[0];
  const float* A      = (const float*)d_in[1];
  const float* conv_w = (const float*)d_in[2];
  const float* conv_b = (const float*)d_in[3];
  const float* enc_w1 = (const float*)d_in[4];
  const float* enc_w2 = (const float*)d_in[5];
  const float* enc_b  = (const float*)d_in[6];
  const float* dec_w  = (const float*)d_in[7];
  const float* dec_b  = (const float*)d_in[8];
  const float* out_w  = (const float*)d_in[9];
  const float* out_b  = (const float*)d_in[10];
  float* out = (float*)d_out;

  k_init<<<640, 256>>>(ts);
  k_gemm<2, true ><<<EE * 256, 128>>>(A, 0);   // slots 0,1 + rowsum + node mask
  k_gemm<2, false><<<EE * 256, 128>>>(A, 2);   // slots 2,3
  k_gemm<1, false><<<EE * 256, 128>>>(A, 4);   // slot 4

  for (int s = 0; s < PSTEPS; s++) {
    k_step<<<512, 128>>>(conv_w, conv_b, enc_w1, enc_w2, enc_b,
                         dec_w, dec_b, out_w, out_b, out, s);
    if (s < PSTEPS - 1)
      k_gemm<1, false><<<EE * 256, 128>>>(A, s % 5);
  }
}